// round 1
// baseline (speedup 1.0000x reference)
#include <cuda_runtime.h>
#include <cstdint>

// ---------------------------------------------------------------------------
// Problem constants (fixed shapes)
// ---------------------------------------------------------------------------
#define BATCH   2048          // windows
#define NTOK    49            // tokens per window
#define HEADS   16
#define HDIM    32
#define CDIM    512           // HEADS*HDIM
#define MW      64            // windows per image (mask groups)
#define MTOT    (BATCH*NTOK)  // 100352 rows
#define QKVCOLS (3*CDIM)      // 1536

// Scratch for Q|K|V, layout [MTOT][1536] (q: cols 0..511, k: 512..1023, v: 1024..1535)
__device__ float g_qkv[(size_t)MTOT * QKVCOLS];

// ---------------------------------------------------------------------------
// Kernel 1: fused QKV projection GEMM
//   out[t][j] = sum_k hidden[t][k] * W[j%512][k] + bias[j%512]
//   W selected from {wq,wk,wv} by j/512.
// Tiling: BM=128, BN=64, BK=16, 256 threads, 8x4 per-thread register tile.
// ---------------------------------------------------------------------------
#define BM 128
#define BN 64
#define BK 16
#define AS_STRIDE 132   // BM + 4 padding (de-conflicts transposed STS)
#define BS_STRIDE 68    // BN + 4 padding

__global__ __launch_bounds__(256) void qkv_gemm(
    const float* __restrict__ hidden,
    const float* __restrict__ wq, const float* __restrict__ bq,
    const float* __restrict__ wk, const float* __restrict__ bk,
    const float* __restrict__ wv, const float* __restrict__ bv)
{
    __shared__ __align__(16) float As[BK * AS_STRIDE];
    __shared__ __align__(16) float Bs[BK * BS_STRIDE];

    const int tid = threadIdx.x;
    const int m0  = blockIdx.y * BM;
    const int jg0 = blockIdx.x * BN;

    const float* wptr = wq; const float* bptr = bq;
    if (jg0 >= 1024)     { wptr = wv; bptr = bv; }
    else if (jg0 >= 512) { wptr = wk; bptr = bk; }
    const int jl0 = jg0 & 511;

    const int tx = tid & 15;   // N sub-tile: cols tx*4 .. tx*4+3
    const int ty = tid >> 4;   // M sub-tile: rows ty*8 .. ty*8+7

    float acc[8][4];
#pragma unroll
    for (int i = 0; i < 8; ++i)
#pragma unroll
        for (int j = 0; j < 4; ++j) acc[i][j] = 0.f;

    const int lrow = tid >> 2;   // 0..63
    const int lk4  = tid & 3;    // which float4 along K

    for (int kt = 0; kt < CDIM; kt += BK) {
        // ---- load A tile: 128 x 16 (two float4 per thread), store k-major
#pragma unroll
        for (int u = 0; u < 2; ++u) {
            const int row = lrow + u * 64;
            const float4 v = *(const float4*)(hidden + (size_t)(m0 + row) * CDIM + kt + lk4 * 4);
            As[(lk4 * 4 + 0) * AS_STRIDE + row] = v.x;
            As[(lk4 * 4 + 1) * AS_STRIDE + row] = v.y;
            As[(lk4 * 4 + 2) * AS_STRIDE + row] = v.z;
            As[(lk4 * 4 + 3) * AS_STRIDE + row] = v.w;
        }
        // ---- load B tile: 64 x 16 (one float4 per thread), store k-major
        {
            const float4 v = *(const float4*)(wptr + (size_t)(jl0 + lrow) * CDIM + kt + lk4 * 4);
            Bs[(lk4 * 4 + 0) * BS_STRIDE + lrow] = v.x;
            Bs[(lk4 * 4 + 1) * BS_STRIDE + lrow] = v.y;
            Bs[(lk4 * 4 + 2) * BS_STRIDE + lrow] = v.z;
            Bs[(lk4 * 4 + 3) * BS_STRIDE + lrow] = v.w;
        }
        __syncthreads();

#pragma unroll
        for (int k = 0; k < BK; ++k) {
            const float4 a0 = *(const float4*)&As[k * AS_STRIDE + ty * 8];
            const float4 a1 = *(const float4*)&As[k * AS_STRIDE + ty * 8 + 4];
            const float4 b  = *(const float4*)&Bs[k * BS_STRIDE + tx * 4];
            const float a[8] = {a0.x, a0.y, a0.z, a0.w, a1.x, a1.y, a1.z, a1.w};
            const float bb[4] = {b.x, b.y, b.z, b.w};
#pragma unroll
            for (int i = 0; i < 8; ++i)
#pragma unroll
                for (int j = 0; j < 4; ++j)
                    acc[i][j] += a[i] * bb[j];
        }
        __syncthreads();
    }

    // ---- epilogue: add bias, store float4
    const float4 bias4 = *(const float4*)(bptr + jl0 + tx * 4);
#pragma unroll
    for (int i = 0; i < 8; ++i) {
        const int row = m0 + ty * 8 + i;
        float4 o;
        o.x = acc[i][0] + bias4.x;
        o.y = acc[i][1] + bias4.y;
        o.z = acc[i][2] + bias4.z;
        o.w = acc[i][3] + bias4.w;
        *(float4*)&g_qkv[(size_t)row * QKVCOLS + jg0 + tx * 4] = o;
    }
}

// ---------------------------------------------------------------------------
// Kernel 2: attention per (window b, head h). 128 threads (4 warps).
//   scores = q.k^T / sqrt(32) + bias_table[relidx][h] + mask[b%64]
//   softmax fused with PV product (probs live in registers, shfl-broadcast)
// ---------------------------------------------------------------------------
#define ROWP 36   // q/k/v smem row stride (floats) -> conflict-free float4 LDS
#define SCP  50   // score row stride

__global__ __launch_bounds__(128) void attn(
    const float* __restrict__ mask,
    const float* __restrict__ bias_table,
    float* __restrict__ out)
{
    __shared__ __align__(16) float qs[NTOK * ROWP];
    __shared__ __align__(16) float ks[NTOK * ROWP];
    __shared__ __align__(16) float vs[NTOK * ROWP];
    __shared__ float sc[NTOK * SCP];

    const int tid = threadIdx.x;
    const int bh  = blockIdx.x;
    const int b   = bh >> 4;
    const int h   = bh & 15;

    // ---- load q/k/v tiles (49 x 32 each) into smem
    const float* base = g_qkv + (size_t)b * NTOK * QKVCOLS + h * HDIM;
    for (int t = tid; t < NTOK * 8; t += 128) {   // 49 rows * 8 float4
        const int n = t >> 3, f = t & 7;
        const float* rp = base + (size_t)n * QKVCOLS + f * 4;
        const float4 q4 = *(const float4*)(rp);
        const float4 k4 = *(const float4*)(rp + 512);
        const float4 v4 = *(const float4*)(rp + 1024);
        *(float4*)&qs[n * ROWP + f * 4] = q4;
        *(float4*)&ks[n * ROWP + f * 4] = k4;
        *(float4*)&vs[n * ROWP + f * 4] = v4;
    }
    __syncthreads();

    // ---- scores with fused relative-position bias + shifted-window mask
    const float* mrow = mask + (size_t)(b & (MW - 1)) * (NTOK * NTOK);
    for (int e = tid; e < NTOK * NTOK; e += 128) {
        const int i = e / NTOK;
        const int j = e - i * NTOK;
        const float* qp = &qs[i * ROWP];
        const float* kp = &ks[j * ROWP];
        float s = 0.f;
#pragma unroll
        for (int dg = 0; dg < 8; ++dg) {
            const float4 q4 = *(const float4*)(qp + dg * 4);
            const float4 k4 = *(const float4*)(kp + dg * 4);
            s += q4.x * k4.x + q4.y * k4.y + q4.z * k4.z + q4.w * k4.w;
        }
        s *= 0.17677669529663687f;   // 1/sqrt(32)
        const int iy = i / 7, ix = i - iy * 7;
        const int jy = j / 7, jx = j - jy * 7;
        const int ridx = (iy - jy + 6) * 13 + (ix - jx + 6);
        s += bias_table[ridx * HEADS + h];
        s += mrow[e];
        sc[i * SCP + j] = s;
    }
    __syncthreads();

    // ---- per-row softmax fused with PV product (warp per row)
    const int warp = tid >> 5;
    const int lane = tid & 31;
    for (int r = warp; r < NTOK; r += 4) {
        const float s0 = sc[r * SCP + lane];
        const float s1 = (lane < 17) ? sc[r * SCP + 32 + lane] : -3.4e38f;
        float m = fmaxf(s0, s1);
#pragma unroll
        for (int o = 16; o > 0; o >>= 1)
            m = fmaxf(m, __shfl_xor_sync(0xffffffffu, m, o));
        const float e0 = __expf(s0 - m);
        const float e1 = (lane < 17) ? __expf(s1 - m) : 0.f;
        float sum = e0 + e1;
#pragma unroll
        for (int o = 16; o > 0; o >>= 1)
            sum += __shfl_xor_sync(0xffffffffu, sum, o);
        const float inv = __frcp_rn(sum);
        const float p0 = e0 * inv;
        const float p1 = e1 * inv;

        float acc = 0.f;
#pragma unroll
        for (int j = 0; j < NTOK; ++j) {
            const float pj = (j < 32) ? __shfl_sync(0xffffffffu, p0, j)
                                      : __shfl_sync(0xffffffffu, p1, j - 32);
            acc += pj * vs[j * ROWP + lane];
        }
        out[((size_t)b * NTOK + r) * CDIM + h * HDIM + lane] = acc;
    }
}

// ---------------------------------------------------------------------------
// Launch
// inputs: 0 hidden, 1 attention_mask, 2 wq, 3 bq, 4 wk, 5 bk, 6 wv, 7 bv, 8 bias_table
// ---------------------------------------------------------------------------
extern "C" void kernel_launch(void* const* d_in, const int* in_sizes, int n_in,
                              void* d_out, int out_size)
{
    const float* hidden = (const float*)d_in[0];
    const float* mask   = (const float*)d_in[1];
    const float* wq     = (const float*)d_in[2];
    const float* bq     = (const float*)d_in[3];
    const float* wk     = (const float*)d_in[4];
    const float* bk     = (const float*)d_in[5];
    const float* wv     = (const float*)d_in[6];
    const float* bv     = (const float*)d_in[7];
    const float* btab   = (const float*)d_in[8];
    float* out = (float*)d_out;

    dim3 g1(QKVCOLS / BN, MTOT / BM);   // 24 x 784
    qkv_gemm<<<g1, 256>>>(hidden, wq, bq, wk, bk, wv, bv);

    attn<<<BATCH * HEADS, 128>>>(mask, btab, out);
}

// round 4
// speedup vs baseline: 1.6688x; 1.6688x over previous
#include <cuda_runtime.h>
#include <cuda_bf16.h>
#include <cstdint>

// ---------------------------------------------------------------------------
// Problem constants
// ---------------------------------------------------------------------------
#define BATCH   2048
#define NTOK    49
#define HEADS   16
#define HDIM    32
#define CDIM    512
#define MW      64
#define MTOT    (BATCH*NTOK)   // 100352
#define QKVCOLS (3*CDIM)       // 1536

__device__ float g_qkv[(size_t)MTOT * QKVCOLS];
__device__ __nv_bfloat16 g_ah[(size_t)MTOT * CDIM];   // hidden hi
__device__ __nv_bfloat16 g_al[(size_t)MTOT * CDIM];   // hidden lo
__device__ __nv_bfloat16 g_wh[(size_t)QKVCOLS * CDIM]; // weights hi (q|k|v rows)
__device__ __nv_bfloat16 g_wl[(size_t)QKVCOLS * CDIM]; // weights lo

// ---------------------------------------------------------------------------
// helpers
// ---------------------------------------------------------------------------
__device__ __forceinline__ uint32_t smem_u32(const void* p) {
    uint32_t a;
    asm("{ .reg .u64 t; cvta.to.shared.u64 t, %1; cvt.u32.u64 %0, t; }" : "=r"(a) : "l"(p));
    return a;
}
__device__ __forceinline__ void cp16(uint32_t saddr, const void* gaddr) {
    asm volatile("cp.async.cg.shared.global [%0], [%1], 16;" :: "r"(saddr), "l"(gaddr) : "memory");
}
__device__ __forceinline__ void cp_commit() {
    asm volatile("cp.async.commit_group;" ::: "memory");
}
template<int N> __device__ __forceinline__ void cp_wait() {
    asm volatile("cp.async.wait_group %0;" :: "n"(N) : "memory");
}
#define LDX4(d, addr) \
    asm volatile("ldmatrix.sync.aligned.m8n8.x4.shared.b16 {%0,%1,%2,%3}, [%4];" \
        : "=r"((d)[0]), "=r"((d)[1]), "=r"((d)[2]), "=r"((d)[3]) : "r"(addr))

__device__ __forceinline__ void mma_bf16(float* c, const uint32_t* a, uint32_t b0, uint32_t b1) {
    asm volatile(
        "mma.sync.aligned.m16n8k16.row.col.f32.bf16.bf16.f32 "
        "{%0,%1,%2,%3}, {%4,%5,%6,%7}, {%8,%9}, {%0,%1,%2,%3};"
        : "+f"(c[0]), "+f"(c[1]), "+f"(c[2]), "+f"(c[3])
        : "r"(a[0]), "r"(a[1]), "r"(a[2]), "r"(a[3]), "r"(b0), "r"(b1));
}

// ---------------------------------------------------------------------------
// Prep: fp32 -> bf16 hi/lo split (8 elements per thread)
// ---------------------------------------------------------------------------
__global__ __launch_bounds__(256) void prep_split(
    const float* __restrict__ x, __nv_bfloat16* __restrict__ hi,
    __nv_bfloat16* __restrict__ lo, int n8)
{
    const int i = blockIdx.x * 256 + threadIdx.x;
    if (i >= n8) return;
    const float4 v0 = ((const float4*)x)[(size_t)i * 2];
    const float4 v1 = ((const float4*)x)[(size_t)i * 2 + 1];
    const float vv[8] = {v0.x, v0.y, v0.z, v0.w, v1.x, v1.y, v1.z, v1.w};
    __nv_bfloat16 h[8], l[8];
#pragma unroll
    for (int j = 0; j < 8; ++j) {
        h[j] = __float2bfloat16(vv[j]);
        l[j] = __float2bfloat16(vv[j] - __bfloat162float(h[j]));
    }
    *(uint4*)(hi + (size_t)i * 8) = *(const uint4*)h;
    *(uint4*)(lo + (size_t)i * 8) = *(const uint4*)l;
}

// ---------------------------------------------------------------------------
// Tensor-core QKV GEMM (mma.sync bf16, 3-pass fp32 emulation)
// BM=128 BN=128 BK=32, 256 threads, warp tile 64x32.
// smem per buffer (halves): AH[128][40], AL, BH[128][40], BL  (40KB); x2 buffers
// ---------------------------------------------------------------------------
#define GBM 128
#define GBN 128
#define GBK 32
#define ASTR 40                   // halves per smem row (padded; ldmatrix conflict-free)
#define HBUF (4 * GBM * ASTR)     // 20480 halves per buffer
#define OFF_AH 0
#define OFF_AL (GBM * ASTR)       // 5120
#define OFF_BH (2 * GBM * ASTR)   // 10240
#define OFF_BL (3 * GBM * ASTR)   // 15360
#define GSMEM  (2 * HBUF * 2)     // 81920 bytes

__global__ __launch_bounds__(256, 2) void qkv_gemm_mma(
    const __nv_bfloat16* __restrict__ ah, const __nv_bfloat16* __restrict__ al,
    const __nv_bfloat16* __restrict__ wh, const __nv_bfloat16* __restrict__ wl,
    const float* __restrict__ bq, const float* __restrict__ bk2,
    const float* __restrict__ bv)
{
    extern __shared__ __align__(16) __nv_bfloat16 sm[];
    const uint32_t sb = smem_u32(sm);
    const int tid  = threadIdx.x;
    const int lane = tid & 31;
    const int w    = tid >> 5;
    const int m0   = blockIdx.y * GBM;
    const int jg0  = blockIdx.x * GBN;

    // staging assignment: thread covers rows r0, r0+64, 16B chunk ch
    const int r0 = tid >> 2;
    const int ch = tid & 3;

    const __nv_bfloat16* gah = ah + (size_t)m0 * CDIM;
    const __nv_bfloat16* gal = al + (size_t)m0 * CDIM;
    const __nv_bfloat16* gwh = wh + (size_t)jg0 * CDIM;
    const __nv_bfloat16* gwl = wl + (size_t)jg0 * CDIM;

    auto issue = [&](int it, int p) {
        const int kt = it * GBK;
        const uint32_t bufb = sb + (uint32_t)(p * HBUF) * 2;
#pragma unroll
        for (int u = 0; u < 2; ++u) {
            const int row = r0 + u * 64;
            const size_t go = (size_t)row * CDIM + kt + ch * 8;
            const uint32_t so = (uint32_t)(row * ASTR + ch * 8) * 2;
            cp16(bufb + OFF_AH * 2 + so, gah + go);
            cp16(bufb + OFF_AL * 2 + so, gal + go);
            cp16(bufb + OFF_BH * 2 + so, gwh + go);
            cp16(bufb + OFF_BL * 2 + so, gwl + go);
        }
    };

    // ldmatrix per-thread addressing
    const int lr = (lane & 7) + ((lane >> 3) & 1) * 8;  // row within 16
    const int lc = (lane >> 4) * 8;                      // col 0 or 8
    const int wm = (w >> 2) * 64;
    const int wn = (w & 3) * 32;

    float acc[4][4][4];
#pragma unroll
    for (int mi = 0; mi < 4; ++mi)
#pragma unroll
        for (int ni = 0; ni < 4; ++ni)
#pragma unroll
            for (int e = 0; e < 4; ++e) acc[mi][ni][e] = 0.f;

    issue(0, 0);
    cp_commit();

    const int NIT = CDIM / GBK;   // 16
    for (int it = 0; it < NIT; ++it) {
        if (it + 1 < NIT) { issue(it + 1, (it + 1) & 1); cp_commit(); cp_wait<1>(); }
        else              { cp_wait<0>(); }
        __syncthreads();

        const uint32_t bufb = sb + (uint32_t)((it & 1) * HBUF) * 2;
#pragma unroll
        for (int ks = 0; ks < 2; ++ks) {
            const int k0 = ks * 16;
            uint32_t AH[4][4], AL[4][4];
#pragma unroll
            for (int mi = 0; mi < 4; ++mi) {
                const uint32_t aoff = bufb + (uint32_t)((wm + mi * 16 + lr) * ASTR + k0 + lc) * 2;
                LDX4(AH[mi], aoff + OFF_AH * 2);
                LDX4(AL[mi], aoff + OFF_AL * 2);
            }
            uint32_t BH[2][4], BL[2][4];
#pragma unroll
            for (int nb = 0; nb < 2; ++nb) {
                const uint32_t boff = bufb + (uint32_t)((wn + nb * 16 + lr) * ASTR + k0 + lc) * 2;
                LDX4(BH[nb], boff + OFF_BH * 2);
                LDX4(BL[nb], boff + OFF_BL * 2);
            }
#pragma unroll
            for (int mi = 0; mi < 4; ++mi)
#pragma unroll
                for (int ni = 0; ni < 4; ++ni) {
                    const int nb = ni >> 1, sel = ni & 1;
                    const uint32_t bh0 = BH[nb][sel], bh1 = BH[nb][sel + 2];
                    const uint32_t bl0 = BL[nb][sel], bl1 = BL[nb][sel + 2];
                    mma_bf16(acc[mi][ni], AH[mi], bh0, bh1);
                    mma_bf16(acc[mi][ni], AH[mi], bl0, bl1);
                    mma_bf16(acc[mi][ni], AL[mi], bh0, bh1);
                }
        }
        __syncthreads();
    }

    // epilogue: + bias, store fp32
    const float* bptr = bq;
    if (jg0 >= 1024)     bptr = bv;
    else if (jg0 >= 512) bptr = bk2;
#pragma unroll
    for (int ni = 0; ni < 4; ++ni) {
        const int jg = jg0 + wn + ni * 8 + 2 * (lane & 3);
        const float b0v = bptr[(jg & 511)];
        const float b1v = bptr[(jg & 511) + 1];
#pragma unroll
        for (int mi = 0; mi < 4; ++mi) {
            const int row = m0 + wm + mi * 16 + (lane >> 2);
            float2 o0 = { acc[mi][ni][0] + b0v, acc[mi][ni][1] + b1v };
            float2 o1 = { acc[mi][ni][2] + b0v, acc[mi][ni][3] + b1v };
            *(float2*)&g_qkv[(size_t)row * QKVCOLS + jg]       = o0;
            *(float2*)&g_qkv[(size_t)(row + 8) * QKVCOLS + jg] = o1;
        }
    }
}

// ---------------------------------------------------------------------------
// Attention per (window b, head h) — unchanged from R1
// ---------------------------------------------------------------------------
#define ROWP 36
#define SCP  50

__global__ __launch_bounds__(128) void attn(
    const float* __restrict__ mask,
    const float* __restrict__ bias_table,
    float* __restrict__ out)
{
    __shared__ __align__(16) float qs[NTOK * ROWP];
    __shared__ __align__(16) float ks[NTOK * ROWP];
    __shared__ __align__(16) float vs[NTOK * ROWP];
    __shared__ float sc[NTOK * SCP];

    const int tid = threadIdx.x;
    const int bh  = blockIdx.x;
    const int b   = bh >> 4;
    const int h   = bh & 15;

    const float* base = g_qkv + (size_t)b * NTOK * QKVCOLS + h * HDIM;
    for (int t = tid; t < NTOK * 8; t += 128) {
        const int n = t >> 3, f = t & 7;
        const float* rp = base + (size_t)n * QKVCOLS + f * 4;
        const float4 q4 = *(const float4*)(rp);
        const float4 k4 = *(const float4*)(rp + 512);
        const float4 v4 = *(const float4*)(rp + 1024);
        *(float4*)&qs[n * ROWP + f * 4] = q4;
        *(float4*)&ks[n * ROWP + f * 4] = k4;
        *(float4*)&vs[n * ROWP + f * 4] = v4;
    }
    __syncthreads();

    const float* mrow = mask + (size_t)(b & (MW - 1)) * (NTOK * NTOK);
    for (int e = tid; e < NTOK * NTOK; e += 128) {
        const int i = e / NTOK;
        const int j = e - i * NTOK;
        const float* qp = &qs[i * ROWP];
        const float* kp = &ks[j * ROWP];
        float s = 0.f;
#pragma unroll
        for (int dg = 0; dg < 8; ++dg) {
            const float4 q4 = *(const float4*)(qp + dg * 4);
            const float4 k4 = *(const float4*)(kp + dg * 4);
            s += q4.x * k4.x + q4.y * k4.y + q4.z * k4.z + q4.w * k4.w;
        }
        s *= 0.17677669529663687f;
        const int iy = i / 7, ix = i - iy * 7;
        const int jy = j / 7, jx = j - jy * 7;
        const int ridx = (iy - jy + 6) * 13 + (ix - jx + 6);
        s += bias_table[ridx * HEADS + h];
        s += mrow[e];
        sc[i * SCP + j] = s;
    }
    __syncthreads();

    const int warp = tid >> 5;
    const int lane = tid & 31;
    for (int r = warp; r < NTOK; r += 4) {
        const float s0 = sc[r * SCP + lane];
        const float s1 = (lane < 17) ? sc[r * SCP + 32 + lane] : -3.4e38f;
        float m = fmaxf(s0, s1);
#pragma unroll
        for (int o = 16; o > 0; o >>= 1)
            m = fmaxf(m, __shfl_xor_sync(0xffffffffu, m, o));
        const float e0 = __expf(s0 - m);
        const float e1 = (lane < 17) ? __expf(s1 - m) : 0.f;
        float sum = e0 + e1;
#pragma unroll
        for (int o = 16; o > 0; o >>= 1)
            sum += __shfl_xor_sync(0xffffffffu, sum, o);
        const float inv = __frcp_rn(sum);
        const float p0 = e0 * inv;
        const float p1 = e1 * inv;

        float acc = 0.f;
#pragma unroll
        for (int j = 0; j < NTOK; ++j) {
            const float pj = (j < 32) ? __shfl_sync(0xffffffffu, p0, j)
                                      : __shfl_sync(0xffffffffu, p1, j - 32);
            acc += pj * vs[j * ROWP + lane];
        }
        out[((size_t)b * NTOK + r) * CDIM + h * HDIM + lane] = acc;
    }
}

// ---------------------------------------------------------------------------
// Launch
// ---------------------------------------------------------------------------
extern "C" void kernel_launch(void* const* d_in, const int* in_sizes, int n_in,
                              void* d_out, int out_size)
{
    const float* hidden = (const float*)d_in[0];
    const float* mask   = (const float*)d_in[1];
    const float* wq     = (const float*)d_in[2];
    const float* bq     = (const float*)d_in[3];
    const float* wk     = (const float*)d_in[4];
    const float* bk     = (const float*)d_in[5];
    const float* wv     = (const float*)d_in[6];
    const float* bv     = (const float*)d_in[7];
    const float* btab   = (const float*)d_in[8];
    float* out = (float*)d_out;

    __nv_bfloat16 *ah, *al, *wh, *wl;
    cudaGetSymbolAddress((void**)&ah, g_ah);
    cudaGetSymbolAddress((void**)&al, g_al);
    cudaGetSymbolAddress((void**)&wh, g_wh);
    cudaGetSymbolAddress((void**)&wl, g_wl);

    // split hidden
    {
        const int n8 = MTOT * CDIM / 8;
        prep_split<<<(n8 + 255) / 256, 256>>>(hidden, ah, al, n8);
    }
    // split weights (q|k|v concatenated rows)
    {
        const int n8 = CDIM * CDIM / 8;
        prep_split<<<(n8 + 255) / 256, 256>>>(wq, wh,                 wl,                 n8);
        prep_split<<<(n8 + 255) / 256, 256>>>(wk, wh + 512 * CDIM,    wl + 512 * CDIM,    n8);
        prep_split<<<(n8 + 255) / 256, 256>>>(wv, wh + 1024 * CDIM,   wl + 1024 * CDIM,   n8);
    }

    cudaFuncSetAttribute(qkv_gemm_mma, cudaFuncAttributeMaxDynamicSharedMemorySize, GSMEM);
    dim3 g1(QKVCOLS / GBN, MTOT / GBM);   // 12 x 784
    qkv_gemm_mma<<<g1, 256, GSMEM>>>(ah, al, wh, wl, bq, bk, bv);

    attn<<<BATCH * HEADS, 128>>>(mask, btab, out);
}